// round 1
// baseline (speedup 1.0000x reference)
#include <cuda_runtime.h>
#include <cstdint>

// ---------------- problem constants ----------------
#define B_   4
#define S_   12
#define N_   512
#define CIN  3
#define COUT 3
#define HID_ 64
#define HEADS_ 8
#define DH_  8
#define L_   2
#define E_   8192
#define BSN  (B_*S_*N_)          // 24576
#define BS_  (B_*S_)             // 48
#define SCALE_ 0.35355339059327373f

// ---------------- device scratch (no runtime alloc allowed) ----------------
__device__ float g_h[BSN * HID_];
__device__ float g_q[BSN * HID_];
__device__ float g_k[BSN * HID_];
__device__ float g_v[BSN * HID_];
__device__ unsigned char g_mask[N_ * N_];

// ---------------- mask build ----------------
__global__ void mask_zero_kernel() {
    int i = blockIdx.x * blockDim.x + threadIdx.x;   // 65536 words
    ((uint32_t*)g_mask)[i] = 0u;
}

__global__ void mask_scatter_kernel(const int* __restrict__ ei) {
    int e = blockIdx.x * blockDim.x + threadIdx.x;
    if (e < E_) {
        int src = ei[e];
        int dst = ei[E_ + e];
        g_mask[src * N_ + dst] = 1;
    }
}

// ---------------- input projection: h = x @ Win^T + b_in ----------------
__global__ void in_proj_kernel(const float* __restrict__ x,
                               const float* __restrict__ Win,
                               const float* __restrict__ b_in) {
    int idx = blockIdx.x * blockDim.x + threadIdx.x;  // BSN*HID
    int j = idx & 63;
    int r = idx >> 6;
    const float* xr = x + r * 3;
    const float* w  = Win + j * 3;
    float s = b_in[j];
    s += xr[0] * w[0];
    s += xr[1] * w[1];
    s += xr[2] * w[2];
    g_h[idx] = s;
}

// ---------------- fused QKV projection ----------------
// block: 256 threads, 64 rows. W staged in padded shared; 4x4 register tiles.
__device__ __forceinline__ void proj_one_mat(const float* __restrict__ hsh,
                                             float* __restrict__ wsh,
                                             const float* __restrict__ W,
                                             const float* __restrict__ bias,
                                             float* __restrict__ out,
                                             int r0, int tid, int jj, int rg) {
    __syncthreads();
#pragma unroll
    for (int i = 0; i < 16; i++) {
        int idx = tid + i * 256;
        int j = idx >> 6, d = idx & 63;
        wsh[j * 65 + d] = W[idx];
    }
    __syncthreads();
    float acc[4][4];
#pragma unroll
    for (int a = 0; a < 4; a++)
#pragma unroll
        for (int b = 0; b < 4; b++) acc[a][b] = 0.f;

#pragma unroll 4
    for (int d = 0; d < 64; d++) {
        float w0 = wsh[(jj * 4 + 0) * 65 + d];
        float w1 = wsh[(jj * 4 + 1) * 65 + d];
        float w2 = wsh[(jj * 4 + 2) * 65 + d];
        float w3 = wsh[(jj * 4 + 3) * 65 + d];
#pragma unroll
        for (int rr = 0; rr < 4; rr++) {
            float hh = hsh[(rg * 4 + rr) * 65 + d];
            acc[rr][0] = fmaf(hh, w0, acc[rr][0]);
            acc[rr][1] = fmaf(hh, w1, acc[rr][1]);
            acc[rr][2] = fmaf(hh, w2, acc[rr][2]);
            acc[rr][3] = fmaf(hh, w3, acc[rr][3]);
        }
    }
    float b0 = bias[jj * 4 + 0];
    float b1 = bias[jj * 4 + 1];
    float b2 = bias[jj * 4 + 2];
    float b3 = bias[jj * 4 + 3];
#pragma unroll
    for (int rr = 0; rr < 4; rr++) {
        float4 o;
        o.x = acc[rr][0] + b0;
        o.y = acc[rr][1] + b1;
        o.z = acc[rr][2] + b2;
        o.w = acc[rr][3] + b3;
        *(float4*)(out + (size_t)(r0 + rg * 4 + rr) * 64 + jj * 4) = o;
    }
}

__global__ __launch_bounds__(256) void qkv_proj_kernel(
    const float* __restrict__ Wq, const float* __restrict__ bq,
    const float* __restrict__ Wk, const float* __restrict__ bk,
    const float* __restrict__ Wv, const float* __restrict__ bv) {
    __shared__ float hsh[64 * 65];
    __shared__ float wsh[64 * 65];
    int tid = threadIdx.x;
    int r0 = blockIdx.x * 64;
#pragma unroll
    for (int i = 0; i < 16; i++) {
        int idx = tid + i * 256;
        int rr = idx >> 6, d = idx & 63;
        hsh[rr * 65 + d] = g_h[(size_t)(r0 + rr) * 64 + d];
    }
    int jj = tid & 15;
    int rg = tid >> 4;
    proj_one_mat(hsh, wsh, Wq, bq, g_q, r0, tid, jj, rg);
    proj_one_mat(hsh, wsh, Wk, bk, g_k, r0, tid, jj, rg);
    proj_one_mat(hsh, wsh, Wv, bv, g_v, r0, tid, jj, rg);
}

// ---------------- spatial attention (flash-style, masked) ----------------
// grid: (8 n-tiles, 48 bs).  512 threads = 8 heads x 64 queries.
// lanes within a warp share head -> all K/V shared reads broadcast.
__global__ __launch_bounds__(512) void spatial_attn_kernel() {
    __shared__ float Ksh[64 * 64];
    __shared__ float Vsh[64 * 64];
    __shared__ unsigned char msk[64 * 64];   // [m][n]

    int tid = threadIdx.x;
    int ntile = blockIdx.x;
    int bs = blockIdx.y;
    int hh = tid >> 6;       // head 0..7
    int nl = tid & 63;       // local query
    int nq = ntile * 64 + nl;

    const float* qrow = g_q + ((size_t)bs * N_ + nq) * 64 + hh * 8;
    float4 q0 = *(const float4*)qrow;
    float4 q1 = *(const float4*)(qrow + 4);

    float m_run = -1e30f, l_run = 0.f;
    float acc[8];
#pragma unroll
    for (int d = 0; d < 8; d++) acc[d] = 0.f;

    for (int mc = 0; mc < 8; mc++) {
        __syncthreads();
        // stage K,V chunk (64 keys x 64 dims)
        const float4* kg = (const float4*)(g_k + ((size_t)bs * N_ + mc * 64) * 64);
        const float4* vg = (const float4*)(g_v + ((size_t)bs * N_ + mc * 64) * 64);
        float4* K4 = (float4*)Ksh;
        float4* V4 = (float4*)Vsh;
        K4[tid] = kg[tid];
        K4[tid + 512] = kg[tid + 512];
        V4[tid] = vg[tid];
        V4[tid + 512] = vg[tid + 512];
        // stage mask tile transposed to [m][n]
        {
            int n = tid >> 3;
            int mb = (tid & 7) * 8;
            const unsigned char* gm = g_mask + (size_t)(ntile * 64 + n) * N_ + mc * 64 + mb;
            unsigned long long w = *(const unsigned long long*)gm;
#pragma unroll
            for (int i = 0; i < 8; i++)
                msk[(mb + i) * 64 + n] = (unsigned char)(w >> (8 * i));
        }
        __syncthreads();

#pragma unroll 1
        for (int mm = 0; mm < 64; mm += 16) {
            float sc[16];
            float cmax = -1e9f;
#pragma unroll
            for (int i = 0; i < 16; i++) {
                int m = mm + i;
                const float* kr = Ksh + m * 64 + hh * 8;
                float4 k0 = *(const float4*)kr;
                float4 k1 = *(const float4*)(kr + 4);
                float dot = q0.x * k0.x + q0.y * k0.y + q0.z * k0.z + q0.w * k0.w
                          + q1.x * k1.x + q1.y * k1.y + q1.z * k1.z + q1.w * k1.w;
                sc[i] = msk[m * 64 + nl] ? dot * SCALE_ : -1e9f;
                cmax = fmaxf(cmax, sc[i]);
            }
            float m_new = fmaxf(m_run, cmax);
            float f = __expf(m_run - m_new);
            l_run *= f;
#pragma unroll
            for (int d = 0; d < 8; d++) acc[d] *= f;
#pragma unroll
            for (int i = 0; i < 16; i++) {
                int m = mm + i;
                float p = __expf(sc[i] - m_new);
                l_run += p;
                const float* vr = Vsh + m * 64 + hh * 8;
                float4 v0 = *(const float4*)vr;
                float4 v1 = *(const float4*)(vr + 4);
                acc[0] = fmaf(p, v0.x, acc[0]);
                acc[1] = fmaf(p, v0.y, acc[1]);
                acc[2] = fmaf(p, v0.z, acc[2]);
                acc[3] = fmaf(p, v0.w, acc[3]);
                acc[4] = fmaf(p, v1.x, acc[4]);
                acc[5] = fmaf(p, v1.y, acc[5]);
                acc[6] = fmaf(p, v1.z, acc[6]);
                acc[7] = fmaf(p, v1.w, acc[7]);
            }
            m_run = m_new;
        }
    }
    float inv = 1.f / l_run;
    float* orow = g_h + ((size_t)bs * N_ + nq) * 64 + hh * 8;
    float4 o0, o1;
    o0.x = acc[0] * inv; o0.y = acc[1] * inv; o0.z = acc[2] * inv; o0.w = acc[3] * inv;
    o1.x = acc[4] * inv; o1.y = acc[5] * inv; o1.z = acc[6] * inv; o1.w = acc[7] * inv;
    *(float4*)orow = o0;
    *(float4*)(orow + 4) = o1;
}

// ---------------- temporal attention (S=12, no mask) ----------------
// one block per (b, n), 128 threads; threads 0..95 = (s, head)
__global__ __launch_bounds__(128) void temporal_attn_kernel() {
    __shared__ float ksh[12 * 64];
    __shared__ float vsh[12 * 64];
    int tid = threadIdx.x;
    int b = blockIdx.x >> 9;
    int n = blockIdx.x & 511;
    for (int i = tid; i < 12 * 64; i += 128) {
        int t = i >> 6, c = i & 63;
        size_t g = (((size_t)b * 12 + t) * N_ + n) * 64 + c;
        ksh[i] = g_k[g];
        vsh[i] = g_v[g];
    }
    __syncthreads();
    if (tid < 96) {
        int s = tid >> 3, hh = tid & 7;
        const float* qr = g_q + (((size_t)b * 12 + s) * N_ + n) * 64 + hh * 8;
        float qv[8];
#pragma unroll
        for (int d = 0; d < 8; d++) qv[d] = qr[d];
        float sc[12];
        float mx = -1e30f;
#pragma unroll
        for (int t = 0; t < 12; t++) {
            float dot = 0.f;
#pragma unroll
            for (int d = 0; d < 8; d++) dot = fmaf(qv[d], ksh[t * 64 + hh * 8 + d], dot);
            sc[t] = dot * SCALE_;
            mx = fmaxf(mx, sc[t]);
        }
        float l = 0.f;
#pragma unroll
        for (int t = 0; t < 12; t++) {
            sc[t] = __expf(sc[t] - mx);
            l += sc[t];
        }
        float acc[8];
#pragma unroll
        for (int d = 0; d < 8; d++) acc[d] = 0.f;
#pragma unroll
        for (int t = 0; t < 12; t++) {
#pragma unroll
            for (int d = 0; d < 8; d++)
                acc[d] = fmaf(sc[t], vsh[t * 64 + hh * 8 + d], acc[d]);
        }
        float inv = 1.f / l;
        float* orow = g_h + (((size_t)b * 12 + s) * N_ + n) * 64 + hh * 8;
#pragma unroll
        for (int d = 0; d < 8; d++) orow[d] = acc[d] * inv;
    }
}

// ---------------- output projection ----------------
__global__ void out_proj_kernel(const float* __restrict__ Wout,
                                const float* __restrict__ bout,
                                float* __restrict__ out) {
    int idx = blockIdx.x * blockDim.x + threadIdx.x;  // 4*512*3 = 6144
    if (idx >= B_ * N_ * COUT) return;
    int j = idx % 3;
    int n = (idx / 3) & 511;
    int b = idx / (3 * N_);
    const float* hr = g_h + (((size_t)b * 12 + 11) * N_ + n) * 64;
    const float* w = Wout + j * 64;
    float s = bout[j];
#pragma unroll 8
    for (int d = 0; d < 64; d++) s = fmaf(hr[d], w[d], s);
    out[idx] = s;
}

// ---------------- launch ----------------
extern "C" void kernel_launch(void* const* d_in, const int* in_sizes, int n_in,
                              void* d_out, int out_size) {
    const float* x    = (const float*)d_in[0];
    const int*   ei   = (const int*)d_in[1];
    const float* Win  = (const float*)d_in[2];
    const float* b_in = (const float*)d_in[3];
    const float* Wqs  = (const float*)d_in[4];
    const float* bqs  = (const float*)d_in[5];
    const float* Wks  = (const float*)d_in[6];
    const float* bks  = (const float*)d_in[7];
    const float* Wvs  = (const float*)d_in[8];
    const float* bvs  = (const float*)d_in[9];
    const float* Wqt  = (const float*)d_in[10];
    const float* bqt  = (const float*)d_in[11];
    const float* Wkt  = (const float*)d_in[12];
    const float* bkt  = (const float*)d_in[13];
    const float* Wvt  = (const float*)d_in[14];
    const float* bvt  = (const float*)d_in[15];
    const float* Wout = (const float*)d_in[16];
    const float* bout = (const float*)d_in[17];
    float* out = (float*)d_out;

    mask_zero_kernel<<<256, 256>>>();
    mask_scatter_kernel<<<(E_ + 255) / 256, 256>>>(ei);
    in_proj_kernel<<<(BSN * HID_) / 256, 256>>>(x, Win, b_in);

    for (int l = 0; l < L_; l++) {
        qkv_proj_kernel<<<BSN / 64, 256>>>(Wqs + l * 4096, bqs + l * 64,
                                           Wks + l * 4096, bks + l * 64,
                                           Wvs + l * 4096, bvs + l * 64);
        spatial_attn_kernel<<<dim3(8, BS_), 512>>>();
        qkv_proj_kernel<<<BSN / 64, 256>>>(Wqt + l * 4096, bqt + l * 64,
                                           Wkt + l * 4096, bkt + l * 64,
                                           Wvt + l * 4096, bvt + l * 64);
        temporal_attn_kernel<<<B_ * N_, 128>>>();
    }
    out_proj_kernel<<<(B_ * N_ * COUT + 255) / 256, 256>>>(Wout, bout, out);
}

// round 2
// speedup vs baseline: 1.1281x; 1.1281x over previous
#include <cuda_runtime.h>
#include <cstdint>

// ---------------- problem constants ----------------
#define B_   4
#define S_   12
#define N_   512
#define CIN  3
#define COUT 3
#define HID_ 64
#define HEADS_ 8
#define DH_  8
#define L_   2
#define E_   8192
#define BSN  (B_*S_*N_)          // 24576
#define BS_  (B_*S_)             // 48
#define SCALE_ 0.35355339059327373f

typedef unsigned long long u64;

// ---------------- f32x2 packed helpers (sm_100+) ----------------
__device__ __forceinline__ u64 pk2(float lo, float hi) {
    u64 r; asm("mov.b64 %0, {%1,%2};" : "=l"(r) : "f"(lo), "f"(hi)); return r;
}
__device__ __forceinline__ void upk2(u64 v, float& lo, float& hi) {
    asm("mov.b64 {%0,%1}, %2;" : "=f"(lo), "=f"(hi) : "l"(v));
}
__device__ __forceinline__ u64 fma2(u64 a, u64 b, u64 c) {
    u64 d; asm("fma.rn.f32x2 %0, %1, %2, %3;" : "=l"(d) : "l"(a), "l"(b), "l"(c)); return d;
}
__device__ __forceinline__ u64 mul2(u64 a, u64 b) {
    u64 d; asm("mul.rn.f32x2 %0, %1, %2;" : "=l"(d) : "l"(a), "l"(b)); return d;
}

// ---------------- device scratch ----------------
__device__ float g_h[BSN * HID_];
__device__ float g_q[BSN * HID_];
__device__ float g_k[BSN * HID_];
__device__ float g_v[BSN * HID_];
__device__ u64   g_mbits[N_ * 8];      // bitmask: row n, 512 key-bits

// ---------------- mask build (bitmask) ----------------
__global__ void mask_zero_kernel() {
    int i = blockIdx.x * blockDim.x + threadIdx.x;   // 4096
    g_mbits[i] = 0ull;
}

__global__ void mask_scatter_kernel(const int* __restrict__ ei) {
    int e = blockIdx.x * blockDim.x + threadIdx.x;
    if (e < E_) {
        int src = ei[e];
        int dst = ei[E_ + e];
        atomicOr(((unsigned int*)g_mbits) + src * 16 + (dst >> 5), 1u << (dst & 31));
    }
}

// ---------------- input projection ----------------
__global__ void in_proj_kernel(const float* __restrict__ x,
                               const float* __restrict__ Win,
                               const float* __restrict__ b_in) {
    int idx = blockIdx.x * blockDim.x + threadIdx.x;
    int j = idx & 63;
    int r = idx >> 6;
    const float* xr = x + r * 3;
    const float* w  = Win + j * 3;
    float s = b_in[j];
    s += xr[0] * w[0];
    s += xr[1] * w[1];
    s += xr[2] * w[2];
    g_h[idx] = s;
}

// ---------------- fused QKV projection, f32x2 microkernel ----------------
// block 256 thr, 64 rows. hP2[d][r] dup-packed h; wT[d][j] transposed W.
// XOR swizzle (granularity 4 elems) keeps reads conflict-free without padding.
__shared__ u64   sm_hP2[64 * 64];    // 32KB
__shared__ float sm_wT[64 * 64];     // 16KB  (total 48KB exactly)

__device__ __forceinline__ void proj_one(const float* __restrict__ W,
                                         const float* __restrict__ bias,
                                         float* __restrict__ out,
                                         int r0, int tid, int jj, int rg) {
    __syncthreads();
#pragma unroll
    for (int i = 0; i < 16; i++) {
        int idx = tid + i * 256;
        int j = idx >> 6, d = idx & 63;
        sm_wT[d * 64 + ((((j >> 2) ^ (d & 15)) << 2) | (j & 3))] = W[idx];
    }
    __syncthreads();

    u64 acc[4][2];
#pragma unroll
    for (int a = 0; a < 4; a++) { acc[a][0] = 0ull; acc[a][1] = 0ull; }

#pragma unroll 16
    for (int d = 0; d < 64; d++) {
        int dx = d & 15;
        const ulonglong2* hp = (const ulonglong2*)(sm_hP2 + d * 64 + ((rg ^ dx) << 2));
        ulonglong2 ha = hp[0];
        ulonglong2 hb = hp[1];
        ulonglong2 wv = *(const ulonglong2*)(sm_wT + d * 64 + ((jj ^ dx) << 2));
        acc[0][0] = fma2(ha.x, wv.x, acc[0][0]);
        acc[0][1] = fma2(ha.x, wv.y, acc[0][1]);
        acc[1][0] = fma2(ha.y, wv.x, acc[1][0]);
        acc[1][1] = fma2(ha.y, wv.y, acc[1][1]);
        acc[2][0] = fma2(hb.x, wv.x, acc[2][0]);
        acc[2][1] = fma2(hb.x, wv.y, acc[2][1]);
        acc[3][0] = fma2(hb.y, wv.x, acc[3][0]);
        acc[3][1] = fma2(hb.y, wv.y, acc[3][1]);
    }
    float b0 = bias[jj * 4 + 0];
    float b1 = bias[jj * 4 + 1];
    float b2 = bias[jj * 4 + 2];
    float b3 = bias[jj * 4 + 3];
#pragma unroll
    for (int rr = 0; rr < 4; rr++) {
        float c0, c1, c2, c3;
        upk2(acc[rr][0], c0, c1);
        upk2(acc[rr][1], c2, c3);
        float4 o;
        o.x = c0 + b0; o.y = c1 + b1; o.z = c2 + b2; o.w = c3 + b3;
        *(float4*)(out + (size_t)(r0 + rg * 4 + rr) * 64 + jj * 4) = o;
    }
}

__global__ __launch_bounds__(256) void qkv_proj_kernel(
    const float* __restrict__ Wq, const float* __restrict__ bq,
    const float* __restrict__ Wk, const float* __restrict__ bk,
    const float* __restrict__ Wv, const float* __restrict__ bv) {
    int tid = threadIdx.x;
    int r0 = blockIdx.x * 64;
#pragma unroll
    for (int i = 0; i < 16; i++) {
        int idx = tid + i * 256;
        int rr = idx >> 6, d = idx & 63;
        float v = g_h[(size_t)(r0 + rr) * 64 + d];
        sm_hP2[d * 64 + ((((rr >> 2) ^ (d & 15)) << 2) | (rr & 3))] = pk2(v, v);
    }
    int jj = tid & 15;
    int rg = tid >> 4;
    proj_one(Wq, bq, g_q, r0, tid, jj, rg);
    proj_one(Wk, bk, g_k, r0, tid, jj, rg);
    proj_one(Wv, bv, g_v, r0, tid, jj, rg);
}

// ---------------- spatial attention (flash-style, bitmask, f32x2) ----------------
// grid (8 n-tiles, 48 bs), 512 threads = 8 heads x 64 queries.
__global__ __launch_bounds__(512) void spatial_attn_kernel() {
    __shared__ float Ksh[64 * 64];      // 16KB
    __shared__ float Vsh[64 * 64];      // 16KB
    __shared__ u64   sbits[8 * 64];     // 4KB: [chunk][query]

    int tid = threadIdx.x;
    int ntile = blockIdx.x;
    int bs = blockIdx.y;
    int hh = tid >> 6;       // head 0..7 (uniform per warp)
    int nl = tid & 63;       // local query
    int nq = ntile * 64 + nl;

    // stage mask bits once: [chunk][query]
    {
        int c = tid & 7, n = tid >> 3;  // tid<512 -> n 0..63
        sbits[c * 64 + n] = g_mbits[(size_t)(ntile * 64 + n) * 8 + c];
    }

    // load + pre-scale + pack q
    const float* qrow = g_q + ((size_t)bs * N_ + nq) * 64 + hh * 8;
    float4 qa = *(const float4*)qrow;
    float4 qb = *(const float4*)(qrow + 4);
    u64 q0 = pk2(qa.x * SCALE_, qa.y * SCALE_);
    u64 q1 = pk2(qa.z * SCALE_, qa.w * SCALE_);
    u64 q2 = pk2(qb.x * SCALE_, qb.y * SCALE_);
    u64 q3 = pk2(qb.z * SCALE_, qb.w * SCALE_);

    float m_run = -1e30f, l_run = 0.f;
    u64 acc0 = 0ull, acc1 = 0ull, acc2 = 0ull, acc3 = 0ull;

    for (int mc = 0; mc < 8; mc++) {
        __syncthreads();
        const float4* kg = (const float4*)(g_k + ((size_t)bs * N_ + mc * 64) * 64);
        const float4* vg = (const float4*)(g_v + ((size_t)bs * N_ + mc * 64) * 64);
        float4* K4 = (float4*)Ksh;
        float4* V4 = (float4*)Vsh;
        K4[tid] = kg[tid];
        K4[tid + 512] = kg[tid + 512];
        V4[tid] = vg[tid];
        V4[tid + 512] = vg[tid + 512];
        __syncthreads();

        u64 bits = sbits[mc * 64 + nl];

#pragma unroll 1
        for (int mm = 0; mm < 64; mm += 16) {
            unsigned w = (unsigned)(bits >> mm) & 0xFFFFu;
            float sc[16];
            float cmax = -1e30f;
#pragma unroll
            for (int i = 0; i < 16; i++) {
                const ulonglong2* kp = (const ulonglong2*)(Ksh + (mm + i) * 64 + hh * 8);
                ulonglong2 ka = kp[0];
                ulonglong2 kb = kp[1];
                u64 t = mul2(q0, ka.x);
                t = fma2(q1, ka.y, t);
                t = fma2(q2, kb.x, t);
                t = fma2(q3, kb.y, t);
                float lo, hi;
                upk2(t, lo, hi);
                float s = ((w >> i) & 1u) ? (lo + hi) : -1e9f;
                sc[i] = s;
                cmax = fmaxf(cmax, s);
            }
            float m_new = fmaxf(m_run, cmax);
            float f = __expf(m_run - m_new);
            l_run *= f;
            u64 f2 = pk2(f, f);
            acc0 = mul2(acc0, f2);
            acc1 = mul2(acc1, f2);
            acc2 = mul2(acc2, f2);
            acc3 = mul2(acc3, f2);
#pragma unroll
            for (int i = 0; i < 16; i++) {
                float p = __expf(sc[i] - m_new);
                l_run += p;
                u64 p2 = pk2(p, p);
                const ulonglong2* vp = (const ulonglong2*)(Vsh + (mm + i) * 64 + hh * 8);
                ulonglong2 va = vp[0];
                ulonglong2 vb = vp[1];
                acc0 = fma2(p2, va.x, acc0);
                acc1 = fma2(p2, va.y, acc1);
                acc2 = fma2(p2, vb.x, acc2);
                acc3 = fma2(p2, vb.y, acc3);
            }
            m_run = m_new;
        }
    }
    float inv = 1.f / l_run;
    float o0, o1, o2, o3, o4, o5, o6, o7;
    upk2(acc0, o0, o1);
    upk2(acc1, o2, o3);
    upk2(acc2, o4, o5);
    upk2(acc3, o6, o7);
    float* orow = g_h + ((size_t)bs * N_ + nq) * 64 + hh * 8;
    float4 w0, w1;
    w0.x = o0 * inv; w0.y = o1 * inv; w0.z = o2 * inv; w0.w = o3 * inv;
    w1.x = o4 * inv; w1.y = o5 * inv; w1.z = o6 * inv; w1.w = o7 * inv;
    *(float4*)orow = w0;
    *(float4*)(orow + 4) = w1;
}

// ---------------- temporal attention (S=12, no mask) ----------------
__global__ __launch_bounds__(128) void temporal_attn_kernel() {
    __shared__ float ksh[12 * 64];
    __shared__ float vsh[12 * 64];
    int tid = threadIdx.x;
    int b = blockIdx.x >> 9;
    int n = blockIdx.x & 511;
    for (int i = tid; i < 12 * 64; i += 128) {
        int t = i >> 6, c = i & 63;
        size_t g = (((size_t)b * 12 + t) * N_ + n) * 64 + c;
        ksh[i] = g_k[g];
        vsh[i] = g_v[g];
    }
    __syncthreads();
    if (tid < 96) {
        int s = tid >> 3, hh = tid & 7;
        const float* qr = g_q + (((size_t)b * 12 + s) * N_ + n) * 64 + hh * 8;
        float qv[8];
#pragma unroll
        for (int d = 0; d < 8; d++) qv[d] = qr[d];
        float sc[12];
        float mx = -1e30f;
#pragma unroll
        for (int t = 0; t < 12; t++) {
            float dot = 0.f;
#pragma unroll
            for (int d = 0; d < 8; d++) dot = fmaf(qv[d], ksh[t * 64 + hh * 8 + d], dot);
            sc[t] = dot * SCALE_;
            mx = fmaxf(mx, sc[t]);
        }
        float l = 0.f;
#pragma unroll
        for (int t = 0; t < 12; t++) {
            sc[t] = __expf(sc[t] - mx);
            l += sc[t];
        }
        float acc[8];
#pragma unroll
        for (int d = 0; d < 8; d++) acc[d] = 0.f;
#pragma unroll
        for (int t = 0; t < 12; t++) {
#pragma unroll
            for (int d = 0; d < 8; d++)
                acc[d] = fmaf(sc[t], vsh[t * 64 + hh * 8 + d], acc[d]);
        }
        float inv = 1.f / l;
        float* orow = g_h + (((size_t)b * 12 + s) * N_ + n) * 64 + hh * 8;
#pragma unroll
        for (int d = 0; d < 8; d++) orow[d] = acc[d] * inv;
    }
}

// ---------------- output projection ----------------
__global__ void out_proj_kernel(const float* __restrict__ Wout,
                                const float* __restrict__ bout,
                                float* __restrict__ out) {
    int idx = blockIdx.x * blockDim.x + threadIdx.x;
    if (idx >= B_ * N_ * COUT) return;
    int j = idx % 3;
    int n = (idx / 3) & 511;
    int b = idx / (3 * N_);
    const float* hr = g_h + (((size_t)b * 12 + 11) * N_ + n) * 64;
    const float* w = Wout + j * 64;
    float s = bout[j];
#pragma unroll 8
    for (int d = 0; d < 64; d++) s = fmaf(hr[d], w[d], s);
    out[idx] = s;
}

// ---------------- launch ----------------
extern "C" void kernel_launch(void* const* d_in, const int* in_sizes, int n_in,
                              void* d_out, int out_size) {
    const float* x    = (const float*)d_in[0];
    const int*   ei   = (const int*)d_in[1];
    const float* Win  = (const float*)d_in[2];
    const float* b_in = (const float*)d_in[3];
    const float* Wqs  = (const float*)d_in[4];
    const float* bqs  = (const float*)d_in[5];
    const float* Wks  = (const float*)d_in[6];
    const float* bks  = (const float*)d_in[7];
    const float* Wvs  = (const float*)d_in[8];
    const float* bvs  = (const float*)d_in[9];
    const float* Wqt  = (const float*)d_in[10];
    const float* bqt  = (const float*)d_in[11];
    const float* Wkt  = (const float*)d_in[12];
    const float* bkt  = (const float*)d_in[13];
    const float* Wvt  = (const float*)d_in[14];
    const float* bvt  = (const float*)d_in[15];
    const float* Wout = (const float*)d_in[16];
    const float* bout = (const float*)d_in[17];
    float* out = (float*)d_out;

    mask_zero_kernel<<<16, 256>>>();
    mask_scatter_kernel<<<(E_ + 255) / 256, 256>>>(ei);
    in_proj_kernel<<<(BSN * HID_) / 256, 256>>>(x, Win, b_in);

    for (int l = 0; l < L_; l++) {
        qkv_proj_kernel<<<BSN / 64, 256>>>(Wqs + l * 4096, bqs + l * 64,
                                           Wks + l * 4096, bks + l * 64,
                                           Wvs + l * 4096, bvs + l * 64);
        spatial_attn_kernel<<<dim3(8, BS_), 512>>>();
        qkv_proj_kernel<<<BSN / 64, 256>>>(Wqt + l * 4096, bqt + l * 64,
                                           Wkt + l * 4096, bkt + l * 64,
                                           Wvt + l * 4096, bvt + l * 64);
        temporal_attn_kernel<<<B_ * N_, 128>>>();
    }
    out_proj_kernel<<<(B_ * N_ * COUT + 255) / 256, 256>>>(Wout, bout, out);
}

// round 3
// speedup vs baseline: 1.9981x; 1.7713x over previous
#include <cuda_runtime.h>
#include <cstdint>

// ---------------- problem constants ----------------
#define B_   4
#define S_   12
#define N_   512
#define CIN  3
#define COUT 3
#define HID_ 64
#define HEADS_ 8
#define DH_  8
#define L_   2
#define E_   8192
#define BSN  (B_*S_*N_)          // 24576
#define BS_  (B_*S_)             // 48
#define SCALE_ 0.35355339059327373f

typedef unsigned long long u64;

// ---------------- f32x2 packed helpers (sm_100+) ----------------
__device__ __forceinline__ u64 pk2(float lo, float hi) {
    u64 r; asm("mov.b64 %0, {%1,%2};" : "=l"(r) : "f"(lo), "f"(hi)); return r;
}
__device__ __forceinline__ void upk2(u64 v, float& lo, float& hi) {
    asm("mov.b64 {%0,%1}, %2;" : "=f"(lo), "=f"(hi) : "l"(v));
}
__device__ __forceinline__ u64 fma2(u64 a, u64 b, u64 c) {
    u64 d; asm("fma.rn.f32x2 %0, %1, %2, %3;" : "=l"(d) : "l"(a), "l"(b), "l"(c)); return d;
}
__device__ __forceinline__ u64 mul2(u64 a, u64 b) {
    u64 d; asm("mul.rn.f32x2 %0, %1, %2;" : "=l"(d) : "l"(a), "l"(b)); return d;
}

// ---------------- device scratch ----------------
__device__ float g_h[BSN * HID_];
__device__ float g_q[BSN * HID_];
__device__ float g_k[BSN * HID_];
__device__ float g_v[BSN * HID_];
__device__ u64   g_mbits[N_ * 8];      // bitmask: row n, 512 key-bits

// ---------------- mask build (bitmask) ----------------
__global__ void mask_zero_kernel() {
    int i = blockIdx.x * blockDim.x + threadIdx.x;   // 4096
    g_mbits[i] = 0ull;
}

__global__ void mask_scatter_kernel(const int* __restrict__ ei) {
    int e = blockIdx.x * blockDim.x + threadIdx.x;
    if (e < E_) {
        int src = ei[e];
        int dst = ei[E_ + e];
        atomicOr(((unsigned int*)g_mbits) + src * 16 + (dst >> 5), 1u << (dst & 31));
    }
}

// ---------------- input projection ----------------
__global__ void in_proj_kernel(const float* __restrict__ x,
                               const float* __restrict__ Win,
                               const float* __restrict__ b_in) {
    int idx = blockIdx.x * blockDim.x + threadIdx.x;
    int j = idx & 63;
    int r = idx >> 6;
    const float* xr = x + r * 3;
    const float* w  = Win + j * 3;
    float s = b_in[j];
    s += xr[0] * w[0];
    s += xr[1] * w[1];
    s += xr[2] * w[2];
    g_h[idx] = s;
}

// ---------------- QKV projection ----------------
// grid (192 row-tiles, 3 matrices), 256 threads.
// 128 rows x 64 cols per block. Thread tile 8 rows x 4 cols.
// hT[d][r] (stride 132), wT[d][j] (stride 68). f32x2 FMA: row-pairs x dup-w.
#define HT_STRIDE 132
#define WT_STRIDE 68
#define QKV_SMEM ((64*HT_STRIDE + 64*WT_STRIDE) * 4)

__global__ __launch_bounds__(256) void qkv_proj_kernel(
    const float* __restrict__ Wq, const float* __restrict__ bq,
    const float* __restrict__ Wk, const float* __restrict__ bk,
    const float* __restrict__ Wv, const float* __restrict__ bv) {
    extern __shared__ float smem[];
    float* hT = smem;                    // 64 x 132
    float* wT = smem + 64 * HT_STRIDE;   // 64 x 68

    int tid = threadIdx.x;
    int r0 = blockIdx.x * 128;
    int mat = blockIdx.y;
    const float* W    = (mat == 0) ? Wq : (mat == 1) ? Wk : Wv;
    const float* bias = (mat == 0) ? bq : (mat == 1) ? bk : bv;
    float* out        = (mat == 0) ? g_q : (mat == 1) ? g_k : g_v;

#pragma unroll
    for (int i = 0; i < 32; i++) {
        int idx = tid + i * 256;
        int r = idx >> 6, d = idx & 63;
        hT[d * HT_STRIDE + r] = g_h[(size_t)(r0 + r) * 64 + d];
    }
#pragma unroll
    for (int i = 0; i < 16; i++) {
        int idx = tid + i * 256;
        int j = idx >> 6, d = idx & 63;
        wT[d * WT_STRIDE + j] = W[idx];
    }
    __syncthreads();

    int cg = tid & 15;    // cols cg*4..+3
    int rg = tid >> 4;    // rows rg*8..+7

    u64 acc[4][4];
#pragma unroll
    for (int a = 0; a < 4; a++)
#pragma unroll
        for (int b = 0; b < 4; b++) acc[a][b] = 0ull;

#pragma unroll 8
    for (int d = 0; d < 64; d++) {
        const float4* hp = (const float4*)(hT + d * HT_STRIDE + rg * 8);
        float4 ha = hp[0];
        float4 hb = hp[1];
        float4 wv = *(const float4*)(wT + d * WT_STRIDE + cg * 4);
        u64 h0 = pk2(ha.x, ha.y);
        u64 h1 = pk2(ha.z, ha.w);
        u64 h2 = pk2(hb.x, hb.y);
        u64 h3 = pk2(hb.z, hb.w);
        u64 w0 = pk2(wv.x, wv.x);
        u64 w1 = pk2(wv.y, wv.y);
        u64 w2 = pk2(wv.z, wv.z);
        u64 w3 = pk2(wv.w, wv.w);
        acc[0][0] = fma2(h0, w0, acc[0][0]);
        acc[0][1] = fma2(h0, w1, acc[0][1]);
        acc[0][2] = fma2(h0, w2, acc[0][2]);
        acc[0][3] = fma2(h0, w3, acc[0][3]);
        acc[1][0] = fma2(h1, w0, acc[1][0]);
        acc[1][1] = fma2(h1, w1, acc[1][1]);
        acc[1][2] = fma2(h1, w2, acc[1][2]);
        acc[1][3] = fma2(h1, w3, acc[1][3]);
        acc[2][0] = fma2(h2, w0, acc[2][0]);
        acc[2][1] = fma2(h2, w1, acc[2][1]);
        acc[2][2] = fma2(h2, w2, acc[2][2]);
        acc[2][3] = fma2(h2, w3, acc[2][3]);
        acc[3][0] = fma2(h3, w0, acc[3][0]);
        acc[3][1] = fma2(h3, w1, acc[3][1]);
        acc[3][2] = fma2(h3, w2, acc[3][2]);
        acc[3][3] = fma2(h3, w3, acc[3][3]);
    }

    float4 bv4 = *(const float4*)(bias + cg * 4);
#pragma unroll
    for (int rp = 0; rp < 4; rp++) {
        float lo0, hi0, lo1, hi1, lo2, hi2, lo3, hi3;
        upk2(acc[rp][0], lo0, hi0);
        upk2(acc[rp][1], lo1, hi1);
        upk2(acc[rp][2], lo2, hi2);
        upk2(acc[rp][3], lo3, hi3);
        size_t rowA = (size_t)(r0 + rg * 8 + rp * 2);
        float4 oA, oB;
        oA.x = lo0 + bv4.x; oA.y = lo1 + bv4.y; oA.z = lo2 + bv4.z; oA.w = lo3 + bv4.w;
        oB.x = hi0 + bv4.x; oB.y = hi1 + bv4.y; oB.z = hi2 + bv4.z; oB.w = hi3 + bv4.w;
        *(float4*)(out + rowA * 64 + cg * 4) = oA;
        *(float4*)(out + (rowA + 1) * 64 + cg * 4) = oB;
    }
}

// ---------------- sparse spatial attention ----------------
// Only ~16 of 512 keys per query are unmasked (E=8192). Iterate set bits,
// read K/V head-slices (32B, sector aligned) directly from global/L2.
// grid (16 q-tiles, 48 bs), 256 threads = 8 heads x 32 queries.
__global__ __launch_bounds__(256) void spatial_attn_kernel() {
    int tid = threadIdx.x;
    int bs = blockIdx.y;
    int hh = tid >> 5;               // head (uniform per warp)
    int nq = blockIdx.x * 32 + (tid & 31);

    const float* qrow = g_q + ((size_t)bs * N_ + nq) * 64 + hh * 8;
    float4 qa = *(const float4*)qrow;
    float4 qb = *(const float4*)(qrow + 4);
    u64 q0 = pk2(qa.x * SCALE_, qa.y * SCALE_);
    u64 q1 = pk2(qa.z * SCALE_, qa.w * SCALE_);
    u64 q2 = pk2(qb.x * SCALE_, qb.y * SCALE_);
    u64 q3 = pk2(qb.z * SCALE_, qb.w * SCALE_);

    const float* kbase = g_k + (size_t)bs * N_ * 64 + hh * 8;
    const float* vbase = g_v + (size_t)bs * N_ * 64 + hh * 8;
    const u64* mrow = g_mbits + (size_t)nq * 8;

    float m_run = -1e30f, l_run = 0.f;
    u64 a0 = 0ull, a1 = 0ull, a2 = 0ull, a3 = 0ull;

#pragma unroll 1
    for (int c = 0; c < 8; c++) {
        u64 bits = mrow[c];
        int base = c * 64;
        while (bits) {
            int i = __ffsll(bits) - 1;
            bits &= bits - 1;
            int m = base + i;
            const float4* kp = (const float4*)(kbase + (size_t)m * 64);
            float4 k0 = kp[0];
            float4 k1 = kp[1];
            const float4* vp = (const float4*)(vbase + (size_t)m * 64);
            float4 v0 = vp[0];
            float4 v1 = vp[1];
            u64 t = mul2(q0, pk2(k0.x, k0.y));
            t = fma2(q1, pk2(k0.z, k0.w), t);
            t = fma2(q2, pk2(k1.x, k1.y), t);
            t = fma2(q3, pk2(k1.z, k1.w), t);
            float lo, hi;
            upk2(t, lo, hi);
            float s = lo + hi;
            float m_new = fmaxf(m_run, s);
            float corr = __expf(m_run - m_new);
            float p = __expf(s - m_new);
            l_run = l_run * corr + p;
            u64 c2 = pk2(corr, corr);
            u64 p2 = pk2(p, p);
            a0 = fma2(p2, pk2(v0.x, v0.y), mul2(a0, c2));
            a1 = fma2(p2, pk2(v0.z, v0.w), mul2(a1, c2));
            a2 = fma2(p2, pk2(v1.x, v1.y), mul2(a2, c2));
            a3 = fma2(p2, pk2(v1.z, v1.w), mul2(a3, c2));
            m_run = m_new;
        }
    }

    float o0, o1, o2, o3, o4, o5, o6, o7;
    float inv;
    if (l_run > 0.f) {
        upk2(a0, o0, o1);
        upk2(a1, o2, o3);
        upk2(a2, o4, o5);
        upk2(a3, o6, o7);
        inv = 1.f / l_run;
    } else {
        // no unmasked keys: reference softmax degrades to uniform over all 512
        o0 = o1 = o2 = o3 = o4 = o5 = o6 = o7 = 0.f;
        for (int m = 0; m < N_; m++) {
            const float4* vp = (const float4*)(vbase + (size_t)m * 64);
            float4 v0 = vp[0];
            float4 v1 = vp[1];
            o0 += v0.x; o1 += v0.y; o2 += v0.z; o3 += v0.w;
            o4 += v1.x; o5 += v1.y; o6 += v1.z; o7 += v1.w;
        }
        inv = 1.f / (float)N_;
    }

    float* orow = g_h + ((size_t)bs * N_ + nq) * 64 + hh * 8;
    float4 w0, w1;
    w0.x = o0 * inv; w0.y = o1 * inv; w0.z = o2 * inv; w0.w = o3 * inv;
    w1.x = o4 * inv; w1.y = o5 * inv; w1.z = o6 * inv; w1.w = o7 * inv;
    *(float4*)orow = w0;
    *(float4*)(orow + 4) = w1;
}

// ---------------- temporal attention (S=12, no mask) ----------------
__global__ __launch_bounds__(128) void temporal_attn_kernel() {
    __shared__ float ksh[12 * 64];
    __shared__ float vsh[12 * 64];
    int tid = threadIdx.x;
    int b = blockIdx.x >> 9;
    int n = blockIdx.x & 511;
    for (int i = tid; i < 12 * 64; i += 128) {
        int t = i >> 6, c = i & 63;
        size_t g = (((size_t)b * 12 + t) * N_ + n) * 64 + c;
        ksh[i] = g_k[g];
        vsh[i] = g_v[g];
    }
    __syncthreads();
    if (tid < 96) {
        int s = tid >> 3, hh = tid & 7;
        const float* qr = g_q + (((size_t)b * 12 + s) * N_ + n) * 64 + hh * 8;
        float qv[8];
#pragma unroll
        for (int d = 0; d < 8; d++) qv[d] = qr[d];
        float sc[12];
        float mx = -1e30f;
#pragma unroll
        for (int t = 0; t < 12; t++) {
            float dot = 0.f;
#pragma unroll
            for (int d = 0; d < 8; d++) dot = fmaf(qv[d], ksh[t * 64 + hh * 8 + d], dot);
            sc[t] = dot * SCALE_;
            mx = fmaxf(mx, sc[t]);
        }
        float l = 0.f;
#pragma unroll
        for (int t = 0; t < 12; t++) {
            sc[t] = __expf(sc[t] - mx);
            l += sc[t];
        }
        float acc[8];
#pragma unroll
        for (int d = 0; d < 8; d++) acc[d] = 0.f;
#pragma unroll
        for (int t = 0; t < 12; t++) {
#pragma unroll
            for (int d = 0; d < 8; d++)
                acc[d] = fmaf(sc[t], vsh[t * 64 + hh * 8 + d], acc[d]);
        }
        float inv = 1.f / l;
        float* orow = g_h + (((size_t)b * 12 + s) * N_ + n) * 64 + hh * 8;
#pragma unroll
        for (int d = 0; d < 8; d++) orow[d] = acc[d] * inv;
    }
}

// ---------------- output projection ----------------
__global__ void out_proj_kernel(const float* __restrict__ Wout,
                                const float* __restrict__ bout,
                                float* __restrict__ out) {
    int idx = blockIdx.x * blockDim.x + threadIdx.x;
    if (idx >= B_ * N_ * COUT) return;
    int j = idx % 3;
    int n = (idx / 3) & 511;
    int b = idx / (3 * N_);
    const float* hr = g_h + (((size_t)b * 12 + 11) * N_ + n) * 64;
    const float* w = Wout + j * 64;
    float s = bout[j];
#pragma unroll 8
    for (int d = 0; d < 64; d++) s = fmaf(hr[d], w[d], s);
    out[idx] = s;
}

// ---------------- launch ----------------
extern "C" void kernel_launch(void* const* d_in, const int* in_sizes, int n_in,
                              void* d_out, int out_size) {
    const float* x    = (const float*)d_in[0];
    const int*   ei   = (const int*)d_in[1];
    const float* Win  = (const float*)d_in[2];
    const float* b_in = (const float*)d_in[3];
    const float* Wqs  = (const float*)d_in[4];
    const float* bqs  = (const float*)d_in[5];
    const float* Wks  = (const float*)d_in[6];
    const float* bks  = (const float*)d_in[7];
    const float* Wvs  = (const float*)d_in[8];
    const float* bvs  = (const float*)d_in[9];
    const float* Wqt  = (const float*)d_in[10];
    const float* bqt  = (const float*)d_in[11];
    const float* Wkt  = (const float*)d_in[12];
    const float* bkt  = (const float*)d_in[13];
    const float* Wvt  = (const float*)d_in[14];
    const float* bvt  = (const float*)d_in[15];
    const float* Wout = (const float*)d_in[16];
    const float* bout = (const float*)d_in[17];
    float* out = (float*)d_out;

    cudaFuncSetAttribute(qkv_proj_kernel,
                         cudaFuncAttributeMaxDynamicSharedMemorySize, QKV_SMEM);

    mask_zero_kernel<<<16, 256>>>();
    mask_scatter_kernel<<<(E_ + 255) / 256, 256>>>(ei);
    in_proj_kernel<<<(BSN * HID_) / 256, 256>>>(x, Win, b_in);

    dim3 qkv_grid(BSN / 128, 3);
    for (int l = 0; l < L_; l++) {
        qkv_proj_kernel<<<qkv_grid, 256, QKV_SMEM>>>(
            Wqs + l * 4096, bqs + l * 64,
            Wks + l * 4096, bks + l * 64,
            Wvs + l * 4096, bvs + l * 64);
        spatial_attn_kernel<<<dim3(16, BS_), 256>>>();
        qkv_proj_kernel<<<qkv_grid, 256, QKV_SMEM>>>(
            Wqt + l * 4096, bqt + l * 64,
            Wkt + l * 4096, bkt + l * 64,
            Wvt + l * 4096, bvt + l * 64);
        temporal_attn_kernel<<<B_ * N_, 128>>>();
    }
    out_proj_kernel<<<(B_ * N_ * COUT + 255) / 256, 256>>>(Wout, bout, out);
}